// round 7
// baseline (speedup 1.0000x reference)
#include <cuda_runtime.h>
#include <cstdint>

// out[e, 0:128]   = X[src[e], :]
// out[e, 128:256] = X[dst[e], :]
// X: [N, 128] fp32 (row = 512 B)   indices: [E, 2] int32   out: [E, 256] fp32
//
// 8 chunks/thread, NO register recycling: launch_bounds(256,1) relaxes the
// ptxas register budget so all 8 gathers stay in flight simultaneously
// (R4/R6 both compiled to regs=32 => effective MLP ~4, not 8).
// Warp lanes cover one 512B source row per chunk: warp-uniform idx load +
// 4x128B coalesced gather. 32-bit byte addressing into X (51.2MB < 4GB).
// Evict-first stores keep the output stream from evicting X in L2.

#define CPT 8

__global__ void __launch_bounds__(256, 1) link_embed_gather_kernel(
    const char* __restrict__ Xb,        // byte pointer to X
    const int* __restrict__ idx,
    float4* __restrict__ out,
    int total_chunks)   // E * 64
{
    const int stride = gridDim.x * blockDim.x;
    const int t0 = blockIdx.x * blockDim.x + threadIdx.x;

    if (t0 + (CPT - 1) * stride < total_chunks) {
        // ---- fast path ----
        unsigned off[CPT];
        #pragma unroll
        for (int i = 0; i < CPT; i++) {
            int t = t0 + i * stride;
            int e = t >> 6;
            int half = (t >> 5) & 1;
            int node = __ldg(&idx[e * 2 + half]);            // warp-uniform
            off[i] = ((unsigned)node << 9) | ((unsigned)(t & 31) << 4);
        }

        // All 8 gathers issued before any store consumes a register.
        float4 v[CPT];
        #pragma unroll
        for (int i = 0; i < CPT; i++)
            v[i] = __ldg((const float4*)(Xb + off[i]));

        #pragma unroll
        for (int i = 0; i < CPT; i++)
            __stcs(&out[t0 + i * stride], v[i]);
    } else {
        // ---- guarded tail (not taken at bench shape) ----
        #pragma unroll 4
        for (int i = 0; i < CPT; i++) {
            int t = t0 + i * stride;
            if (t < total_chunks) {
                int e = t >> 6;
                int half = (t >> 5) & 1;
                int node = __ldg(&idx[e * 2 + half]);
                unsigned off = ((unsigned)node << 9) | ((unsigned)(t & 31) << 4);
                __stcs(&out[t], __ldg((const float4*)(Xb + off)));
            }
        }
    }
}

extern "C" void kernel_launch(void* const* d_in, const int* in_sizes, int n_in,
                              void* d_out, int out_size)
{
    const char* Xb = (const char*)d_in[0];
    const int* idx = (const int*)d_in[1];
    float4* out = (float4*)d_out;

    int E = in_sizes[1] / 2;          // indices has E*2 int32 elements
    int total_chunks = E * 64;

    int threads = 256;
    int chunks_per_block = threads * CPT;
    int blocks = (total_chunks + chunks_per_block - 1) / chunks_per_block;
    link_embed_gather_kernel<<<blocks, threads>>>(Xb, idx, out, total_chunks);
}